// round 15
// baseline (speedup 1.0000x reference)
#include <cuda_runtime.h>
#include <cuda_fp16.h>
#include <stdint.h>
#include <math.h>

#define DIM   128
#define D2    256
#define NI    65536
#define NC    8192
#define EI    524288
#define EC    65536
#define TT    102400
#define SS    2048
#define VV    100000
#define NCAT  1000

// ---------------- scratch (device globals; no allocation allowed) -------------
__device__ float g_item_agg[NI * DIM];
__device__ float g_cat_agg [NC * DIM];
__device__ float g_et      [NI * DIM];
__device__ float g_ft      [NC * DIM];
__device__ float g_alpha   [TT];
__device__ int   g_start   [SS];
__device__ int   g_last    [SS];
// half operands
__device__ __half g_iaggh[NI * DIM], g_iaggl[NI * DIM];
__device__ __half g_caggh[NC * DIM], g_caggl[NC * DIM];
__device__ __half g_eth  [NI * DIM], g_etl  [NI * DIM];
__device__ __half g_fth  [NC * DIM], g_ftl  [NC * DIM];
__device__ __half g_Ueth [NI * D2];
__device__ __half g_Ufth [NC * D2];
__device__ __half g_Vsh  [SS * D2];
__device__ __half g_lastEh[SS * D2], g_lastEl[SS * D2];
__device__ __half g_sgh  [SS * D2];
__device__ __half g_allh [VV * D2];          // fused [item_tab | cat_tab[c4i]] half
__device__ __half g_iWh  [DIM * DIM], g_cWh[DIM * DIM];
__device__ __half g_w1Wh [D2 * D2],   g_w2Wh[D2 * D2];

// ---------------- init ----------------
__global__ void k_init() {
    int i = blockIdx.x * blockDim.x + threadIdx.x;
    if (i < NI * DIM) g_item_agg[i] = 0.f;
    if (i < NC * DIM) g_cat_agg[i]  = 0.f;
    if (i < SS) { g_start[i] = -1; g_last[i] = 0; }
}

// ---------------- combined weight conversions ----------------
__global__ void k_cvtW(const float* __restrict__ a, __half* __restrict__ da, int na,
                       const float* __restrict__ b, __half* __restrict__ db, int nb,
                       const float* __restrict__ c, __half* __restrict__ dc, int nc,
                       const float* __restrict__ d, __half* __restrict__ dd, int nd) {
    int i = blockIdx.x * blockDim.x + threadIdx.x;
    if (i < na) { da[i] = __float2half(a[i]); return; }
    i -= na;
    if (i < nb) { db[i] = __float2half(b[i]); return; }
    i -= nb;
    if (i < nc) { dc[i] = __float2half(c[i]); return; }
    i -= nc;
    if (i < nd) { dd[i] = __float2half(d[i]); }
}

// ---------------- combined hi/lo split of both aggregates -------------------
__global__ void k_split_agg(const float* __restrict__ ia, __half* __restrict__ ih,
                            __half* __restrict__ il,
                            const float* __restrict__ ca, __half* __restrict__ ch,
                            __half* __restrict__ cl) {
    int i = blockIdx.x * blockDim.x + threadIdx.x;
    const float* s; __half *h, *l; int idx;
    if (i < NI * DIM) { s = ia; h = ih; l = il; idx = i; }
    else {
        idx = i - NI * DIM;
        if (idx >= NC * DIM) return;
        s = ca; h = ch; l = cl;
    }
    float x = s[idx];
    __half hh = __float2half(x);
    h[idx] = hh;
    l[idx] = __float2half(x - __half2float(hh));
}

// fused table: all[v, 0:128] = item_tab[v], all[v, 128:256] = cat_tab[c4i[v]]
__global__ void k_fuse(const float* __restrict__ it, const float* __restrict__ ct,
                       const int* __restrict__ c4i, __half* __restrict__ all) {
    int i = blockIdx.x * blockDim.x + threadIdx.x;
    if (i >= VV * D2) return;
    int v = i >> 8, d = i & 255;
    float x = (d < 128) ? it[(size_t)v * DIM + d]
                        : ct[(size_t)c4i[v] * DIM + (d - 128)];
    all[i] = __float2half(x);
}

// ---------------- edge scatter ----------------
__global__ void k_edges(const int* __restrict__ edges, const float* __restrict__ ew,
                        const int* __restrict__ nodemap, const float* __restrict__ table,
                        float* __restrict__ agg, int E) {
    long gid = (long)blockIdx.x * blockDim.x + threadIdx.x;
    if (gid >= (long)E * 32) return;
    int e    = (int)(gid >> 5);
    int lane = (int)(gid & 31);
    int src = edges[e];
    int dst = edges[E + e];
    float w = ew[e];
    int id = nodemap[src];
    float4 v = *(const float4*)(table + (size_t)id * DIM + lane * 4);
    float* o = agg + (size_t)dst * DIM + lane * 4;
    asm volatile("red.global.add.v4.f32 [%0], {%1,%2,%3,%4};"
                 :: "l"(o), "f"(v.x * w), "f"(v.y * w), "f"(v.z * w), "f"(v.w * w)
                 : "memory");
}

// ---------------- fp16 mma + ldmatrix helpers ----------------
__device__ __forceinline__ void mma_f16(float c[4], const unsigned a[4], const unsigned b[2]) {
    asm volatile(
        "mma.sync.aligned.m16n8k16.row.col.f32.f16.f16.f32 "
        "{%0,%1,%2,%3}, {%4,%5,%6,%7}, {%8,%9}, {%0,%1,%2,%3};"
        : "+f"(c[0]), "+f"(c[1]), "+f"(c[2]), "+f"(c[3])
        : "r"(a[0]), "r"(a[1]), "r"(a[2]), "r"(a[3]), "r"(b[0]), "r"(b[1]));
}
__device__ __forceinline__ void ldsm_x4(unsigned r[4], uint32_t addr) {
    asm volatile("ldmatrix.sync.aligned.m8n8.x4.shared.b16 {%0,%1,%2,%3}, [%4];"
                 : "=r"(r[0]), "=r"(r[1]), "=r"(r[2]), "=r"(r[3]) : "r"(addr));
}

// ============ fp16 tensor GEMM: C[M,N] = A[M,K](lda) @ B[N,K]^T(ldb) =========
// SPLIT=1: A = Ah + Al (2 MMA chains). SPLIT=0: single.
// MODE 0: direct store with optional fp32 (Cf,+bias) / half (Ch) / half-lo (Cl)
//         outputs; grid (n, m).
// MODE 1: smem-staged coalesced float4 fp32 store, grid (m, n) for B L2 reuse.
// BK=32. M%128==0, K%32==0. 2-stage cp.async double buffer, ldmatrix frags.
#define PADW  20
#define TILEB (128 * PADW * 4)
template<int SPLIT, int MODE>
__global__ __launch_bounds__(256, 2) void k_hgemm(
    float* __restrict__ Cf, __half* __restrict__ Ch, __half* __restrict__ Cl,
    const __half* __restrict__ Ahg, const __half* __restrict__ Alg,
    int lda, const __half* __restrict__ B, int ldb, int M, int N, int K,
    const float* __restrict__ bias) {
    constexpr int NTILE  = SPLIT ? 3 : 2;
    constexpr int STAGEB = NTILE * TILEB;
    extern __shared__ char sm8[];

    const int tid  = threadIdx.x;
    const int lane = tid & 31;
    const int warp = tid >> 5;
    const int wm = (warp >> 1) * 32;
    const int wn = (warp & 1) * 64;
    const int tg = lane & 3;
    const int gp = lane >> 2;
    const int bm = (MODE == 1 ? blockIdx.x : blockIdx.y) * 128;
    const int bn = (MODE == 1 ? blockIdx.y : blockIdx.x) * 128;
    const uint32_t sbase = (uint32_t)__cvta_generic_to_shared(sm8);

    const uint32_t aoff = (uint32_t)((wm + (lane & 15)) * (PADW * 4) + (lane >> 4) * 16);
    const uint32_t boff = (uint32_t)((wn + (lane & 7) + ((lane >> 4) << 3)) * (PADW * 4)
                                     + ((lane >> 3) & 1) * 16);

    float acc[2][8][4];
#pragma unroll
    for (int mt = 0; mt < 2; mt++)
#pragma unroll
        for (int nt = 0; nt < 8; nt++)
#pragma unroll
            for (int e = 0; e < 4; e++) acc[mt][nt][e] = 0.f;

    const int nIter = K / 32;

#define LOAD_STAGE(stage, k0)                                                           \
    {                                                                                   \
        const uint32_t so_ = sbase + (stage) * STAGEB;                                  \
        _Pragma("unroll")                                                               \
        for (int i_ = 0; i_ < 2; i_++) {                                                \
            int idx_ = i_ * 256 + tid;                                                  \
            int row_ = idx_ >> 2, c_ = idx_ & 3;                                        \
            uint32_t d_ = (uint32_t)(row_ * (PADW * 4) + c_ * 16);                      \
            const __half* pa_ = Ahg + (size_t)(bm + row_) * lda + (k0) + c_ * 8;        \
            asm volatile("cp.async.cg.shared.global [%0], [%1], 16;"                    \
                         :: "r"(so_ + d_), "l"(pa_));                                   \
            if (SPLIT) {                                                                \
                const __half* pl_ = Alg + (size_t)(bm + row_) * lda + (k0) + c_ * 8;    \
                asm volatile("cp.async.cg.shared.global [%0], [%1], 16;"                \
                             :: "r"(so_ + TILEB + d_), "l"(pl_));                       \
            }                                                                           \
            int rb_ = bn + row_; if (rb_ >= N) rb_ = N - 1;                             \
            const __half* pb_ = B + (size_t)rb_ * ldb + (k0) + c_ * 8;                  \
            asm volatile("cp.async.cg.shared.global [%0], [%1], 16;"                    \
                         :: "r"(so_ + (NTILE - 1) * TILEB + d_), "l"(pb_));             \
        }                                                                               \
        asm volatile("cp.async.commit_group;");                                        \
    }

    LOAD_STAGE(0, 0)
    if (nIter > 1) { LOAD_STAGE(1, 32) }
    else           { asm volatile("cp.async.commit_group;"); }

    for (int it = 0; it < nIter; ++it) {
        asm volatile("cp.async.wait_group 1;");
        __syncthreads();
        const uint32_t tA = sbase + (it & 1) * STAGEB;
        const uint32_t tL = tA + TILEB;
        const uint32_t tB = tA + (NTILE - 1) * TILEB;
#pragma unroll
        for (int kk = 0; kk < 2; kk++) {
            const uint32_t kboff = kk * 32;
            unsigned a_h[2][4], b_h[8][2];
            unsigned a_l[SPLIT ? 2 : 1][4];
#pragma unroll
            for (int mt = 0; mt < 2; mt++) {
                ldsm_x4(a_h[mt], tA + aoff + mt * (16 * PADW * 4) + kboff);
                if (SPLIT)
                    ldsm_x4(a_l[mt], tL + aoff + mt * (16 * PADW * 4) + kboff);
            }
#pragma unroll
            for (int p = 0; p < 4; p++) {
                unsigned bb[4];
                ldsm_x4(bb, tB + boff + p * (16 * PADW * 4) + kboff);
                b_h[2 * p][0]     = bb[0]; b_h[2 * p][1]     = bb[1];
                b_h[2 * p + 1][0] = bb[2]; b_h[2 * p + 1][1] = bb[3];
            }
#pragma unroll
            for (int mt = 0; mt < 2; mt++)
#pragma unroll
                for (int nt = 0; nt < 8; nt++) {
                    mma_f16(acc[mt][nt], a_h[mt], b_h[nt]);
                    if (SPLIT) mma_f16(acc[mt][nt], a_l[mt], b_h[nt]);
                }
        }
        __syncthreads();
        if (it + 2 < nIter) { LOAD_STAGE(it & 1, (it + 2) * 32) }
        else                { asm volatile("cp.async.commit_group;"); }
    }
#undef LOAD_STAGE

    if (MODE == 1) {
        __syncthreads();
        float* so = (float*)sm8;   // 128 x 132 floats
#pragma unroll
        for (int mt = 0; mt < 2; mt++) {
            int r0 = wm + mt * 16 + gp;
#pragma unroll
            for (int nt = 0; nt < 8; nt++) {
                int cl = wn + nt * 8 + 2 * tg;
                so[r0 * 132 + cl]           = acc[mt][nt][0];
                so[r0 * 132 + cl + 1]       = acc[mt][nt][1];
                so[(r0 + 8) * 132 + cl]     = acc[mt][nt][2];
                so[(r0 + 8) * 132 + cl + 1] = acc[mt][nt][3];
            }
        }
        __syncthreads();
        int col = lane * 4;
        int cg = bn + col;
        if (cg < N) {
            for (int rr = warp; rr < 128; rr += 8) {
                int rg = bm + rr;
                float4 v = *(const float4*)&so[rr * 132 + col];
                *(float4*)&Cf[(size_t)rg * N + cg] = v;
            }
        }
    } else {
#pragma unroll
        for (int mt = 0; mt < 2; mt++) {
            int row0 = bm + wm + mt * 16 + gp;
#pragma unroll
            for (int nt = 0; nt < 8; nt++) {
                int col = bn + wn + nt * 8 + 2 * tg;
#pragma unroll
                for (int half = 0; half < 2; half++) {
                    int row = row0 + half * 8;
#pragma unroll
                    for (int e = 0; e < 2; e++) {
                        int cc = col + e;
                        if (cc < N) {
                            float v = acc[mt][nt][half * 2 + e];
                            if (bias) v += bias[cc];
                            size_t off = (size_t)row * N + cc;
                            if (Cf) Cf[off] = v;
                            if (Ch) {
                                __half hv = __float2half(v);
                                Ch[off] = hv;
                                if (Cl) Cl[off] = __float2half(v - __half2float(hv));
                            }
                        }
                    }
                }
            }
        }
    }
}

// ---------------- session boundaries ----------------
__global__ void k_bounds(const int* __restrict__ seg) {
    int t = blockIdx.x * blockDim.x + threadIdx.x;
    if (t >= TT) return;
    int s = seg[t];
    if (t == TT - 1 || seg[t + 1] != s) g_last[s]  = t;
    if (t == 0      || seg[t - 1] != s) g_start[s] = t;
}

// ------- lastE (half hi/lo): [et[i2x[last]], ft[c2x[last]]] -----------------
__global__ void k_lastE(const int* __restrict__ i2x, const int* __restrict__ c2x,
                        const float* __restrict__ et, const float* __restrict__ ft,
                        __half* __restrict__ lh, __half* __restrict__ ll) {
    int gid = blockIdx.x * blockDim.x + threadIdx.x;
    if (gid >= SS * D2) return;
    int s = gid >> 8;
    int d = gid & 255;
    int t = g_last[s];
    float x = (d < 128) ? et[(size_t)i2x[t] * DIM + d]
                        : ft[(size_t)c2x[t] * DIM + (d - 128)];
    __half hh = __float2half(x);
    lh[gid] = hh;
    ll[gid] = __float2half(x - __half2float(hh));
}

// --------- FMA-only sigmoid (no MUFU): exp2 poly + Newton reciprocal --------
__device__ __forceinline__ float fsig(float h) {
    float s = h * 1.44269504f;
    s = fminf(fmaxf(s, -126.f), 126.f);
    float n = floorf(s);
    float f = s - n;
    float p = 1.5403530e-4f;
    p = fmaf(p, f, 1.3333558e-3f);
    p = fmaf(p, f, 9.6181291e-3f);
    p = fmaf(p, f, 5.5504109e-2f);
    p = fmaf(p, f, 2.4022651e-1f);
    p = fmaf(p, f, 6.9314718e-1f);
    p = fmaf(p, f, 1.0f);
    float r = __int_as_float(__float_as_int(p) + (((int)n) << 23));   // e^h
    float d = 1.f + r;
    float x = __int_as_float(0x7EF311C3 - __float_as_int(d));
    x = x * (2.f - d * x);
    x = x * (2.f - d * x);
    x = x * (2.f - d * x);
    return r * x;
}

// ------ alpha[t] = q . sigmoid(Uet[i2x[t]] + Uft[c2x[t]] + Vs[seg[t]]) + qb --
__global__ void k_alpha(const __half* __restrict__ Uet, const __half* __restrict__ Uft,
                        const __half* __restrict__ Vs,
                        const int* __restrict__ i2x, const int* __restrict__ c2x,
                        const int* __restrict__ seg, const float* __restrict__ qW,
                        const float* __restrict__ qb, float* __restrict__ alpha) {
    long gid = (long)blockIdx.x * blockDim.x + threadIdx.x;
    int t = (int)(gid >> 5);
    int lane = (int)(gid & 31);
    if (t >= TT) return;
    const __half2* u  = (const __half2*)(Uet + (size_t)i2x[t] * D2);
    const __half2* u2 = (const __half2*)(Uft + (size_t)c2x[t] * D2);
    const __half2* v  = (const __half2*)(Vs  + (size_t)seg[t] * D2);
    float sum = 0.f;
#pragma unroll
    for (int i = lane; i < D2 / 2; i += 32) {
        float2 a = __half22float2(u[i]);
        float2 b = __half22float2(u2[i]);
        float2 c = __half22float2(v[i]);
        float h0 = a.x + b.x + c.x;
        float h1 = a.y + b.y + c.y;
        sum += qW[2 * i] * fsig(h0) + qW[2 * i + 1] * fsig(h1);
    }
#pragma unroll
    for (int o = 16; o; o >>= 1) sum += __shfl_xor_sync(0xFFFFFFFFu, sum, o);
    if (lane == 0) alpha[t] = sum + qb[0];
}

// ------ sg[s,d] (half) = sum_t alpha[t] * ([et[i2x[t]] | ft[c2x[t]]])[d] -----
__global__ void k_sg(const int* __restrict__ i2x, const int* __restrict__ c2x,
                     const float* __restrict__ et, const float* __restrict__ ft,
                     const float* __restrict__ alpha, __half* __restrict__ sgh) {
    int s = blockIdx.x;
    int d = threadIdx.x;  // 256
    float acc = 0.f;
    int st = g_start[s];
    if (st >= 0) {
        int en = g_last[s];
        if (d < 128) {
            for (int t = st; t <= en; ++t)
                acc += alpha[t] * et[(size_t)i2x[t] * DIM + d];
        } else {
            for (int t = st; t <= en; ++t)
                acc += alpha[t] * ft[(size_t)c2x[t] * DIM + (d - 128)];
        }
    }
    sgh[(size_t)s * D2 + d] = __float2half(acc);
}

// ============================ host launcher =================================
extern "C" void kernel_launch(void* const* d_in, const int* in_sizes, int n_in,
                              void* d_out, int out_size) {
    const int*   items    = (const int*)  d_in[0];
    const int*   cats     = (const int*)  d_in[1];
    const int*   item2idx = (const int*)  d_in[2];
    const int*   cat2idx  = (const int*)  d_in[3];
    const int*   item_e   = (const int*)  d_in[4];
    const int*   cat_e    = (const int*)  d_in[5];
    const float* item_ew  = (const float*)d_in[6];
    const float* cat_ew   = (const float*)d_in[7];
    const int*   seg      = (const int*)  d_in[8];
    const int*   cat4item = (const int*)  d_in[9];
    const float* item_tab = (const float*)d_in[10];
    const float* cat_tab  = (const float*)d_in[11];
    const float* iW  = (const float*)d_in[12];
    const float* ib  = (const float*)d_in[13];
    const float* cW  = (const float*)d_in[14];
    const float* cb  = (const float*)d_in[15];
    const float* w1W = (const float*)d_in[16];
    const float* w1b = (const float*)d_in[17];
    const float* w2W = (const float*)d_in[18];
    const float* qW  = (const float*)d_in[19];
    const float* qb  = (const float*)d_in[20];
    float* out = (float*)d_out;

    static float *p_iagg = nullptr, *p_cagg, *p_et, *p_ft, *p_alpha;
    static __half *p_iaggh, *p_iaggl, *p_caggh, *p_caggl, *p_eth, *p_etl,
                  *p_fth, *p_ftl, *p_Ueth, *p_Ufth, *p_Vsh, *p_lEh, *p_lEl,
                  *p_sgh, *p_allh, *p_iWh, *p_cWh, *p_w1Wh, *p_w2Wh;
    if (!p_iagg) {
        cudaGetSymbolAddress((void**)&p_iagg,  g_item_agg);
        cudaGetSymbolAddress((void**)&p_cagg,  g_cat_agg);
        cudaGetSymbolAddress((void**)&p_et,    g_et);
        cudaGetSymbolAddress((void**)&p_ft,    g_ft);
        cudaGetSymbolAddress((void**)&p_alpha, g_alpha);
        cudaGetSymbolAddress((void**)&p_iaggh, g_iaggh);
        cudaGetSymbolAddress((void**)&p_iaggl, g_iaggl);
        cudaGetSymbolAddress((void**)&p_caggh, g_caggh);
        cudaGetSymbolAddress((void**)&p_caggl, g_caggl);
        cudaGetSymbolAddress((void**)&p_eth,   g_eth);
        cudaGetSymbolAddress((void**)&p_etl,   g_etl);
        cudaGetSymbolAddress((void**)&p_fth,   g_fth);
        cudaGetSymbolAddress((void**)&p_ftl,   g_ftl);
        cudaGetSymbolAddress((void**)&p_Ueth,  g_Ueth);
        cudaGetSymbolAddress((void**)&p_Ufth,  g_Ufth);
        cudaGetSymbolAddress((void**)&p_Vsh,   g_Vsh);
        cudaGetSymbolAddress((void**)&p_lEh,   g_lastEh);
        cudaGetSymbolAddress((void**)&p_lEl,   g_lastEl);
        cudaGetSymbolAddress((void**)&p_sgh,   g_sgh);
        cudaGetSymbolAddress((void**)&p_allh,  g_allh);
        cudaGetSymbolAddress((void**)&p_iWh,   g_iWh);
        cudaGetSymbolAddress((void**)&p_cWh,   g_cWh);
        cudaGetSymbolAddress((void**)&p_w1Wh,  g_w1Wh);
        cudaGetSymbolAddress((void**)&p_w2Wh,  g_w2Wh);
        cudaFuncSetAttribute((const void*)k_hgemm<1,0>, cudaFuncAttributeMaxDynamicSharedMemorySize, 69632);
        cudaFuncSetAttribute((const void*)k_hgemm<0,1>, cudaFuncAttributeMaxDynamicSharedMemorySize, 69632);
    }
    const int SMF = 69632;   // MODE1: max(2*2*10240, 128*132*4 = 67584)
    const int SMP = 61440;   // SPLIT: 2 stages * 3 tiles * 10240

    // 1. init + fused output table + combined weight conversions
    k_init<<<(NI * DIM + 255) / 256, 256>>>();
    k_fuse<<<(VV * D2 + 255) / 256, 256>>>(item_tab, cat_tab, cat4item, p_allh);
    {
        int ntot = DIM * DIM * 2 + D2 * D2 * 2;
        k_cvtW<<<(ntot + 255) / 256, 256>>>(iW, p_iWh, DIM * DIM, cW, p_cWh, DIM * DIM,
                                            w1W, p_w1Wh, D2 * D2, w2W, p_w2Wh, D2 * D2);
    }

    // 2. edge scatters + combined hi/lo split of aggregates
    k_edges<<<(EI * 32) / 256, 256>>>(item_e, item_ew, items, item_tab, p_iagg, EI);
    k_edges<<<(EC * 32) / 256, 256>>>(cat_e,  cat_ew,  cats,  cat_tab,  p_cagg, EC);
    k_split_agg<<<((NI + NC) * DIM + 255) / 256, 256>>>(p_iagg, p_iaggh, p_iaggl,
                                                        p_cagg, p_caggh, p_caggl);

    // 3. node GNN linears (fp16 A-split); epilogue writes fp32 + half hi/lo
    { dim3 g(1, NI / 128); k_hgemm<1,0><<<g, 256, SMP>>>(p_et, p_eth, p_etl, p_iaggh, p_iaggl, DIM, p_iWh, DIM, NI, DIM, DIM, ib); }
    { dim3 g(1, NC / 128); k_hgemm<1,0><<<g, 256, SMP>>>(p_ft, p_fth, p_ftl, p_caggh, p_caggl, DIM, p_cWh, DIM, NC, DIM, DIM, cb); }

    // 4. U factorization at node level — half outputs only
    { dim3 g(2, NI / 128); k_hgemm<1,0><<<g, 256, SMP>>>(nullptr, p_Ueth, nullptr, p_eth, p_etl, DIM, p_w1Wh,       D2, NI, D2, DIM, w1b); }
    { dim3 g(2, NC / 128); k_hgemm<1,0><<<g, 256, SMP>>>(nullptr, p_Ufth, nullptr, p_fth, p_ftl, DIM, p_w1Wh + DIM, D2, NC, D2, DIM, nullptr); }

    // 5. session bounds + last embedding + Vs (half output)
    k_bounds<<<TT / 256, 256>>>(seg);
    k_lastE<<<(SS * D2 + 255) / 256, 256>>>(item2idx, cat2idx, p_et, p_ft, p_lEh, p_lEl);
    { dim3 g(2, SS / 128); k_hgemm<1,0><<<g, 256, SMP>>>(nullptr, p_Vsh, nullptr, p_lEh, p_lEl, D2, p_w2Wh, D2, SS, D2, D2, nullptr); }

    // 6. alpha (half U inputs, FMA-only sigmoid) + session aggregation
    k_alpha<<<(TT * 32) / 256, 256>>>(p_Ueth, p_Ufth, p_Vsh, item2idx, cat2idx, seg, qW, qb, p_alpha);
    k_sg<<<SS, 256>>>(item2idx, cat2idx, p_et, p_ft, p_alpha, p_sgh);

    // 7. out = sg @ all_item^T  [S, V], K=256 — grid (m, n) for B L2 reuse
    { dim3 g(SS / 128, (VV + 127) / 128);
      k_hgemm<0,1><<<g, 256, SMF>>>(out, nullptr, nullptr, p_sgh, nullptr, D2, p_allh, D2, SS, VV, D2, nullptr); }
}

// round 17
// speedup vs baseline: 1.0816x; 1.0816x over previous
#include <cuda_runtime.h>
#include <cuda_fp16.h>
#include <stdint.h>
#include <math.h>

#define DIM   128
#define D2    256
#define NI    65536
#define NC    8192
#define EI    524288
#define EC    65536
#define TT    102400
#define SS    2048
#define VV    100000
#define NCAT  1000

// ---------------- scratch (device globals; no allocation allowed) -------------
__device__ float g_item_agg[NI * DIM];
__device__ float g_cat_agg [NC * DIM];
__device__ float g_et      [NI * DIM];
__device__ float g_ft      [NC * DIM];
__device__ float g_alpha   [TT];
__device__ int   g_start   [SS];
__device__ int   g_last    [SS];
// half operands
__device__ __half g_iaggh[NI * DIM], g_iaggl[NI * DIM];
__device__ __half g_caggh[NC * DIM], g_caggl[NC * DIM];
__device__ __half g_eth  [NI * DIM], g_etl  [NI * DIM];
__device__ __half g_fth  [NC * DIM], g_ftl  [NC * DIM];
__device__ __half g_Ueth [NI * D2];
__device__ __half g_Ufth [NC * D2];
__device__ __half g_Vsh  [SS * D2];
__device__ __half g_lastEh[SS * D2], g_lastEl[SS * D2];
__device__ __half g_sgh  [SS * D2];
__device__ __half g_allh [VV * D2];          // fused [item_tab | cat_tab[c4i]] half
__device__ __half g_iWh  [DIM * DIM], g_cWh[DIM * DIM];
__device__ __half g_w1Wh [D2 * D2],   g_w2Wh[D2 * D2];

// ---------------- init ----------------
__global__ void k_init() {
    int i = blockIdx.x * blockDim.x + threadIdx.x;
    if (i < NI * DIM) g_item_agg[i] = 0.f;
    if (i < NC * DIM) g_cat_agg[i]  = 0.f;
    if (i < SS) { g_start[i] = -1; g_last[i] = 0; }
}

// ---------------- combined weight conversions ----------------
__global__ void k_cvtW(const float* __restrict__ a, __half* __restrict__ da, int na,
                       const float* __restrict__ b, __half* __restrict__ db, int nb,
                       const float* __restrict__ c, __half* __restrict__ dc, int nc,
                       const float* __restrict__ d, __half* __restrict__ dd, int nd) {
    int i = blockIdx.x * blockDim.x + threadIdx.x;
    if (i < na) { da[i] = __float2half(a[i]); return; }
    i -= na;
    if (i < nb) { db[i] = __float2half(b[i]); return; }
    i -= nb;
    if (i < nc) { dc[i] = __float2half(c[i]); return; }
    i -= nc;
    if (i < nd) { dd[i] = __float2half(d[i]); }
}

// ---------------- combined hi/lo split of both aggregates -------------------
__global__ void k_split_agg(const float* __restrict__ ia, __half* __restrict__ ih,
                            __half* __restrict__ il,
                            const float* __restrict__ ca, __half* __restrict__ ch,
                            __half* __restrict__ cl) {
    int i = blockIdx.x * blockDim.x + threadIdx.x;
    const float* s; __half *h, *l; int idx;
    if (i < NI * DIM) { s = ia; h = ih; l = il; idx = i; }
    else {
        idx = i - NI * DIM;
        if (idx >= NC * DIM) return;
        s = ca; h = ch; l = cl;
    }
    float x = s[idx];
    __half hh = __float2half(x);
    h[idx] = hh;
    l[idx] = __float2half(x - __half2float(hh));
}

// fused table: all[v, 0:128] = item_tab[v], all[v, 128:256] = cat_tab[c4i[v]]
__global__ void k_fuse(const float* __restrict__ it, const float* __restrict__ ct,
                       const int* __restrict__ c4i, __half* __restrict__ all) {
    int i = blockIdx.x * blockDim.x + threadIdx.x;
    if (i >= VV * D2) return;
    int v = i >> 8, d = i & 255;
    float x = (d < 128) ? it[(size_t)v * DIM + d]
                        : ct[(size_t)c4i[v] * DIM + (d - 128)];
    all[i] = __float2half(x);
}

// ---------------- edge scatter ----------------
__global__ void k_edges(const int* __restrict__ edges, const float* __restrict__ ew,
                        const int* __restrict__ nodemap, const float* __restrict__ table,
                        float* __restrict__ agg, int E) {
    long gid = (long)blockIdx.x * blockDim.x + threadIdx.x;
    if (gid >= (long)E * 32) return;
    int e    = (int)(gid >> 5);
    int lane = (int)(gid & 31);
    int src = edges[e];
    int dst = edges[E + e];
    float w = ew[e];
    int id = nodemap[src];
    float4 v = *(const float4*)(table + (size_t)id * DIM + lane * 4);
    float* o = agg + (size_t)dst * DIM + lane * 4;
    asm volatile("red.global.add.v4.f32 [%0], {%1,%2,%3,%4};"
                 :: "l"(o), "f"(v.x * w), "f"(v.y * w), "f"(v.z * w), "f"(v.w * w)
                 : "memory");
}

// ---------------- fp16 mma + ldmatrix helpers ----------------
__device__ __forceinline__ void mma_f16(float c[4], const unsigned a[4], const unsigned b[2]) {
    asm volatile(
        "mma.sync.aligned.m16n8k16.row.col.f32.f16.f16.f32 "
        "{%0,%1,%2,%3}, {%4,%5,%6,%7}, {%8,%9}, {%0,%1,%2,%3};"
        : "+f"(c[0]), "+f"(c[1]), "+f"(c[2]), "+f"(c[3])
        : "r"(a[0]), "r"(a[1]), "r"(a[2]), "r"(a[3]), "r"(b[0]), "r"(b[1]));
}
__device__ __forceinline__ void ldsm_x4(unsigned r[4], uint32_t addr) {
    asm volatile("ldmatrix.sync.aligned.m8n8.x4.shared.b16 {%0,%1,%2,%3}, [%4];"
                 : "=r"(r[0]), "=r"(r[1]), "=r"(r[2]), "=r"(r[3]) : "r"(addr));
}

// ============ fp16 tensor GEMM: C[M,N] = A[M,K](lda) @ B[N,K]^T(ldb) =========
// SPLIT=1: A = Ah + Al (2 MMA chains). SPLIT=0: single.
// MODE 0: vectorized direct store — float2 (Cf,+bias) / half2 (Ch) / half2 (Cl);
//         grid (n, m). (All MODE-0 uses have N % 2 == 0; guarded anyway.)
// MODE 1: smem-staged coalesced float4 fp32 store, grid (m, n) for B L2 reuse.
// BK=32. M%128==0, K%32==0. 2-stage cp.async double buffer, ldmatrix frags.
#define PADW  20
#define TILEB (128 * PADW * 4)
template<int SPLIT, int MODE>
__global__ __launch_bounds__(256, 2) void k_hgemm(
    float* __restrict__ Cf, __half* __restrict__ Ch, __half* __restrict__ Cl,
    const __half* __restrict__ Ahg, const __half* __restrict__ Alg,
    int lda, const __half* __restrict__ B, int ldb, int M, int N, int K,
    const float* __restrict__ bias) {
    constexpr int NTILE  = SPLIT ? 3 : 2;
    constexpr int STAGEB = NTILE * TILEB;
    extern __shared__ char sm8[];

    const int tid  = threadIdx.x;
    const int lane = tid & 31;
    const int warp = tid >> 5;
    const int wm = (warp >> 1) * 32;
    const int wn = (warp & 1) * 64;
    const int tg = lane & 3;
    const int gp = lane >> 2;
    const int bm = (MODE == 1 ? blockIdx.x : blockIdx.y) * 128;
    const int bn = (MODE == 1 ? blockIdx.y : blockIdx.x) * 128;
    const uint32_t sbase = (uint32_t)__cvta_generic_to_shared(sm8);

    const uint32_t aoff = (uint32_t)((wm + (lane & 15)) * (PADW * 4) + (lane >> 4) * 16);
    const uint32_t boff = (uint32_t)((wn + (lane & 7) + ((lane >> 4) << 3)) * (PADW * 4)
                                     + ((lane >> 3) & 1) * 16);

    float acc[2][8][4];
#pragma unroll
    for (int mt = 0; mt < 2; mt++)
#pragma unroll
        for (int nt = 0; nt < 8; nt++)
#pragma unroll
            for (int e = 0; e < 4; e++) acc[mt][nt][e] = 0.f;

    const int nIter = K / 32;

#define LOAD_STAGE(stage, k0)                                                           \
    {                                                                                   \
        const uint32_t so_ = sbase + (stage) * STAGEB;                                  \
        _Pragma("unroll")                                                               \
        for (int i_ = 0; i_ < 2; i_++) {                                                \
            int idx_ = i_ * 256 + tid;                                                  \
            int row_ = idx_ >> 2, c_ = idx_ & 3;                                        \
            uint32_t d_ = (uint32_t)(row_ * (PADW * 4) + c_ * 16);                      \
            const __half* pa_ = Ahg + (size_t)(bm + row_) * lda + (k0) + c_ * 8;        \
            asm volatile("cp.async.cg.shared.global [%0], [%1], 16;"                    \
                         :: "r"(so_ + d_), "l"(pa_));                                   \
            if (SPLIT) {                                                                \
                const __half* pl_ = Alg + (size_t)(bm + row_) * lda + (k0) + c_ * 8;    \
                asm volatile("cp.async.cg.shared.global [%0], [%1], 16;"                \
                             :: "r"(so_ + TILEB + d_), "l"(pl_));                       \
            }                                                                           \
            int rb_ = bn + row_; if (rb_ >= N) rb_ = N - 1;                             \
            const __half* pb_ = B + (size_t)rb_ * ldb + (k0) + c_ * 8;                  \
            asm volatile("cp.async.cg.shared.global [%0], [%1], 16;"                    \
                         :: "r"(so_ + (NTILE - 1) * TILEB + d_), "l"(pb_));             \
        }                                                                               \
        asm volatile("cp.async.commit_group;");                                        \
    }

    LOAD_STAGE(0, 0)
    if (nIter > 1) { LOAD_STAGE(1, 32) }
    else           { asm volatile("cp.async.commit_group;"); }

    for (int it = 0; it < nIter; ++it) {
        asm volatile("cp.async.wait_group 1;");
        __syncthreads();
        const uint32_t tA = sbase + (it & 1) * STAGEB;
        const uint32_t tL = tA + TILEB;
        const uint32_t tB = tA + (NTILE - 1) * TILEB;
#pragma unroll
        for (int kk = 0; kk < 2; kk++) {
            const uint32_t kboff = kk * 32;
            unsigned a_h[2][4], b_h[8][2];
            unsigned a_l[SPLIT ? 2 : 1][4];
#pragma unroll
            for (int mt = 0; mt < 2; mt++) {
                ldsm_x4(a_h[mt], tA + aoff + mt * (16 * PADW * 4) + kboff);
                if (SPLIT)
                    ldsm_x4(a_l[mt], tL + aoff + mt * (16 * PADW * 4) + kboff);
            }
#pragma unroll
            for (int p = 0; p < 4; p++) {
                unsigned bb[4];
                ldsm_x4(bb, tB + boff + p * (16 * PADW * 4) + kboff);
                b_h[2 * p][0]     = bb[0]; b_h[2 * p][1]     = bb[1];
                b_h[2 * p + 1][0] = bb[2]; b_h[2 * p + 1][1] = bb[3];
            }
#pragma unroll
            for (int mt = 0; mt < 2; mt++)
#pragma unroll
                for (int nt = 0; nt < 8; nt++) {
                    mma_f16(acc[mt][nt], a_h[mt], b_h[nt]);
                    if (SPLIT) mma_f16(acc[mt][nt], a_l[mt], b_h[nt]);
                }
        }
        __syncthreads();
        if (it + 2 < nIter) { LOAD_STAGE(it & 1, (it + 2) * 32) }
        else                { asm volatile("cp.async.commit_group;"); }
    }
#undef LOAD_STAGE

    if (MODE == 1) {
        __syncthreads();
        float* so = (float*)sm8;   // 128 x 132 floats
#pragma unroll
        for (int mt = 0; mt < 2; mt++) {
            int r0 = wm + mt * 16 + gp;
#pragma unroll
            for (int nt = 0; nt < 8; nt++) {
                int cl = wn + nt * 8 + 2 * tg;
                so[r0 * 132 + cl]           = acc[mt][nt][0];
                so[r0 * 132 + cl + 1]       = acc[mt][nt][1];
                so[(r0 + 8) * 132 + cl]     = acc[mt][nt][2];
                so[(r0 + 8) * 132 + cl + 1] = acc[mt][nt][3];
            }
        }
        __syncthreads();
        int col = lane * 4;
        int cg = bn + col;
        if (cg < N) {
            for (int rr = warp; rr < 128; rr += 8) {
                int rg = bm + rr;
                float4 v = *(const float4*)&so[rr * 132 + col];
                *(float4*)&Cf[(size_t)rg * N + cg] = v;
            }
        }
    } else {
#pragma unroll
        for (int mt = 0; mt < 2; mt++) {
            int row0 = bm + wm + mt * 16 + gp;
#pragma unroll
            for (int nt = 0; nt < 8; nt++) {
                int col = bn + wn + nt * 8 + 2 * tg;
#pragma unroll
                for (int half = 0; half < 2; half++) {
                    int row = row0 + half * 8;
                    if (col + 1 < N) {
                        float v0 = acc[mt][nt][half * 2 + 0];
                        float v1 = acc[mt][nt][half * 2 + 1];
                        if (bias) { v0 += bias[col]; v1 += bias[col + 1]; }
                        size_t off = (size_t)row * N + col;
                        if (Cf) *(float2*)&Cf[off] = make_float2(v0, v1);
                        if (Ch) {
                            __half h0 = __float2half(v0), h1 = __float2half(v1);
                            *(__half2*)&Ch[off] = __halves2half2(h0, h1);
                            if (Cl)
                                *(__half2*)&Cl[off] = __halves2half2(
                                    __float2half(v0 - __half2float(h0)),
                                    __float2half(v1 - __half2float(h1)));
                        }
                    } else if (col < N) {
                        float v0 = acc[mt][nt][half * 2 + 0];
                        if (bias) v0 += bias[col];
                        size_t off = (size_t)row * N + col;
                        if (Cf) Cf[off] = v0;
                        if (Ch) {
                            __half h0 = __float2half(v0);
                            Ch[off] = h0;
                            if (Cl) Cl[off] = __float2half(v0 - __half2float(h0));
                        }
                    }
                }
            }
        }
    }
}

// ---------------- session boundaries ----------------
__global__ void k_bounds(const int* __restrict__ seg) {
    int t = blockIdx.x * blockDim.x + threadIdx.x;
    if (t >= TT) return;
    int s = seg[t];
    if (t == TT - 1 || seg[t + 1] != s) g_last[s]  = t;
    if (t == 0      || seg[t - 1] != s) g_start[s] = t;
}

// ------- lastE (half hi/lo): [et[i2x[last]], ft[c2x[last]]] -----------------
__global__ void k_lastE(const int* __restrict__ i2x, const int* __restrict__ c2x,
                        const float* __restrict__ et, const float* __restrict__ ft,
                        __half* __restrict__ lh, __half* __restrict__ ll) {
    int gid = blockIdx.x * blockDim.x + threadIdx.x;
    if (gid >= SS * D2) return;
    int s = gid >> 8;
    int d = gid & 255;
    int t = g_last[s];
    float x = (d < 128) ? et[(size_t)i2x[t] * DIM + d]
                        : ft[(size_t)c2x[t] * DIM + (d - 128)];
    __half hh = __float2half(x);
    lh[gid] = hh;
    ll[gid] = __float2half(x - __half2float(hh));
}

// --------- FMA-only sigmoid (no MUFU): exp2 poly + Newton reciprocal --------
__device__ __forceinline__ float fsig(float h) {
    float s = h * 1.44269504f;
    s = fminf(fmaxf(s, -126.f), 126.f);
    float n = floorf(s);
    float f = s - n;
    float p = 1.5403530e-4f;
    p = fmaf(p, f, 1.3333558e-3f);
    p = fmaf(p, f, 9.6181291e-3f);
    p = fmaf(p, f, 5.5504109e-2f);
    p = fmaf(p, f, 2.4022651e-1f);
    p = fmaf(p, f, 6.9314718e-1f);
    p = fmaf(p, f, 1.0f);
    float r = __int_as_float(__float_as_int(p) + (((int)n) << 23));   // e^h
    float d = 1.f + r;
    float x = __int_as_float(0x7EF311C3 - __float_as_int(d));
    x = x * (2.f - d * x);
    x = x * (2.f - d * x);
    x = x * (2.f - d * x);
    return r * x;
}

// ------ alpha[t] = q . sigmoid(Uet[i2x[t]] + Uft[c2x[t]] + Vs[seg[t]]) + qb --
__global__ void k_alpha(const __half* __restrict__ Uet, const __half* __restrict__ Uft,
                        const __half* __restrict__ Vs,
                        const int* __restrict__ i2x, const int* __restrict__ c2x,
                        const int* __restrict__ seg, const float* __restrict__ qW,
                        const float* __restrict__ qb, float* __restrict__ alpha) {
    long gid = (long)blockIdx.x * blockDim.x + threadIdx.x;
    int t = (int)(gid >> 5);
    int lane = (int)(gid & 31);
    if (t >= TT) return;
    const __half2* u  = (const __half2*)(Uet + (size_t)i2x[t] * D2);
    const __half2* u2 = (const __half2*)(Uft + (size_t)c2x[t] * D2);
    const __half2* v  = (const __half2*)(Vs  + (size_t)seg[t] * D2);
    float sum = 0.f;
#pragma unroll
    for (int i = lane; i < D2 / 2; i += 32) {
        float2 a = __half22float2(u[i]);
        float2 b = __half22float2(u2[i]);
        float2 c = __half22float2(v[i]);
        float h0 = a.x + b.x + c.x;
        float h1 = a.y + b.y + c.y;
        sum += qW[2 * i] * fsig(h0) + qW[2 * i + 1] * fsig(h1);
    }
#pragma unroll
    for (int o = 16; o; o >>= 1) sum += __shfl_xor_sync(0xFFFFFFFFu, sum, o);
    if (lane == 0) alpha[t] = sum + qb[0];
}

// ------ sg[s,d] (half) = sum_t alpha[t] * ([et[i2x[t]] | ft[c2x[t]]])[d] -----
__global__ void k_sg(const int* __restrict__ i2x, const int* __restrict__ c2x,
                     const float* __restrict__ et, const float* __restrict__ ft,
                     const float* __restrict__ alpha, __half* __restrict__ sgh) {
    int s = blockIdx.x;
    int d = threadIdx.x;  // 256
    float acc = 0.f;
    int st = g_start[s];
    if (st >= 0) {
        int en = g_last[s];
        if (d < 128) {
            for (int t = st; t <= en; ++t)
                acc += alpha[t] * et[(size_t)i2x[t] * DIM + d];
        } else {
            for (int t = st; t <= en; ++t)
                acc += alpha[t] * ft[(size_t)c2x[t] * DIM + (d - 128)];
        }
    }
    sgh[(size_t)s * D2 + d] = __float2half(acc);
}

// ============================ host launcher =================================
extern "C" void kernel_launch(void* const* d_in, const int* in_sizes, int n_in,
                              void* d_out, int out_size) {
    const int*   items    = (const int*)  d_in[0];
    const int*   cats     = (const int*)  d_in[1];
    const int*   item2idx = (const int*)  d_in[2];
    const int*   cat2idx  = (const int*)  d_in[3];
    const int*   item_e   = (const int*)  d_in[4];
    const int*   cat_e    = (const int*)  d_in[5];
    const float* item_ew  = (const float*)d_in[6];
    const float* cat_ew   = (const float*)d_in[7];
    const int*   seg      = (const int*)  d_in[8];
    const int*   cat4item = (const int*)  d_in[9];
    const float* item_tab = (const float*)d_in[10];
    const float* cat_tab  = (const float*)d_in[11];
    const float* iW  = (const float*)d_in[12];
    const float* ib  = (const float*)d_in[13];
    const float* cW  = (const float*)d_in[14];
    const float* cb  = (const float*)d_in[15];
    const float* w1W = (const float*)d_in[16];
    const float* w1b = (const float*)d_in[17];
    const float* w2W = (const float*)d_in[18];
    const float* qW  = (const float*)d_in[19];
    const float* qb  = (const float*)d_in[20];
    float* out = (float*)d_out;

    static float *p_iagg = nullptr, *p_cagg, *p_et, *p_ft, *p_alpha;
    static __half *p_iaggh, *p_iaggl, *p_caggh, *p_caggl, *p_eth, *p_etl,
                  *p_fth, *p_ftl, *p_Ueth, *p_Ufth, *p_Vsh, *p_lEh, *p_lEl,
                  *p_sgh, *p_allh, *p_iWh, *p_cWh, *p_w1Wh, *p_w2Wh;
    if (!p_iagg) {
        cudaGetSymbolAddress((void**)&p_iagg,  g_item_agg);
        cudaGetSymbolAddress((void**)&p_cagg,  g_cat_agg);
        cudaGetSymbolAddress((void**)&p_et,    g_et);
        cudaGetSymbolAddress((void**)&p_ft,    g_ft);
        cudaGetSymbolAddress((void**)&p_alpha, g_alpha);
        cudaGetSymbolAddress((void**)&p_iaggh, g_iaggh);
        cudaGetSymbolAddress((void**)&p_iaggl, g_iaggl);
        cudaGetSymbolAddress((void**)&p_caggh, g_caggh);
        cudaGetSymbolAddress((void**)&p_caggl, g_caggl);
        cudaGetSymbolAddress((void**)&p_eth,   g_eth);
        cudaGetSymbolAddress((void**)&p_etl,   g_etl);
        cudaGetSymbolAddress((void**)&p_fth,   g_fth);
        cudaGetSymbolAddress((void**)&p_ftl,   g_ftl);
        cudaGetSymbolAddress((void**)&p_Ueth,  g_Ueth);
        cudaGetSymbolAddress((void**)&p_Ufth,  g_Ufth);
        cudaGetSymbolAddress((void**)&p_Vsh,   g_Vsh);
        cudaGetSymbolAddress((void**)&p_lEh,   g_lastEh);
        cudaGetSymbolAddress((void**)&p_lEl,   g_lastEl);
        cudaGetSymbolAddress((void**)&p_sgh,   g_sgh);
        cudaGetSymbolAddress((void**)&p_allh,  g_allh);
        cudaGetSymbolAddress((void**)&p_iWh,   g_iWh);
        cudaGetSymbolAddress((void**)&p_cWh,   g_cWh);
        cudaGetSymbolAddress((void**)&p_w1Wh,  g_w1Wh);
        cudaGetSymbolAddress((void**)&p_w2Wh,  g_w2Wh);
        cudaFuncSetAttribute((const void*)k_hgemm<1,0>, cudaFuncAttributeMaxDynamicSharedMemorySize, 69632);
        cudaFuncSetAttribute((const void*)k_hgemm<0,1>, cudaFuncAttributeMaxDynamicSharedMemorySize, 69632);
    }
    const int SMF = 69632;   // MODE1: max(2*2*10240, 128*132*4 = 67584)
    const int SMP = 61440;   // SPLIT: 2 stages * 3 tiles * 10240

    // 1. init + fused output table + combined weight conversions
    k_init<<<(NI * DIM + 255) / 256, 256>>>();
    k_fuse<<<(VV * D2 + 255) / 256, 256>>>(item_tab, cat_tab, cat4item, p_allh);
    {
        int ntot = DIM * DIM * 2 + D2 * D2 * 2;
        k_cvtW<<<(ntot + 255) / 256, 256>>>(iW, p_iWh, DIM * DIM, cW, p_cWh, DIM * DIM,
                                            w1W, p_w1Wh, D2 * D2, w2W, p_w2Wh, D2 * D2);
    }

    // 2. edge scatters + combined hi/lo split of aggregates
    k_edges<<<(EI * 32) / 256, 256>>>(item_e, item_ew, items, item_tab, p_iagg, EI);
    k_edges<<<(EC * 32) / 256, 256>>>(cat_e,  cat_ew,  cats,  cat_tab,  p_cagg, EC);
    k_split_agg<<<((NI + NC) * DIM + 255) / 256, 256>>>(p_iagg, p_iaggh, p_iaggl,
                                                        p_cagg, p_caggh, p_caggl);

    // 3. node GNN linears (fp16 A-split); epilogue writes fp32 + half hi/lo
    { dim3 g(1, NI / 128); k_hgemm<1,0><<<g, 256, SMP>>>(p_et, p_eth, p_etl, p_iaggh, p_iaggl, DIM, p_iWh, DIM, NI, DIM, DIM, ib); }
    { dim3 g(1, NC / 128); k_hgemm<1,0><<<g, 256, SMP>>>(p_ft, p_fth, p_ftl, p_caggh, p_caggl, DIM, p_cWh, DIM, NC, DIM, DIM, cb); }

    // 4. U factorization at node level — half outputs only
    { dim3 g(2, NI / 128); k_hgemm<1,0><<<g, 256, SMP>>>(nullptr, p_Ueth, nullptr, p_eth, p_etl, DIM, p_w1Wh,       D2, NI, D2, DIM, w1b); }
    { dim3 g(2, NC / 128); k_hgemm<1,0><<<g, 256, SMP>>>(nullptr, p_Ufth, nullptr, p_fth, p_ftl, DIM, p_w1Wh + DIM, D2, NC, D2, DIM, nullptr); }

    // 5. session bounds + last embedding + Vs (half output)
    k_bounds<<<TT / 256, 256>>>(seg);
    k_lastE<<<(SS * D2 + 255) / 256, 256>>>(item2idx, cat2idx, p_et, p_ft, p_lEh, p_lEl);
    { dim3 g(2, SS / 128); k_hgemm<1,0><<<g, 256, SMP>>>(nullptr, p_Vsh, nullptr, p_lEh, p_lEl, D2, p_w2Wh, D2, SS, D2, D2, nullptr); }

    // 6. alpha (half U inputs, FMA-only sigmoid) + session aggregation
    k_alpha<<<(TT * 32) / 256, 256>>>(p_Ueth, p_Ufth, p_Vsh, item2idx, cat2idx, seg, qW, qb, p_alpha);
    k_sg<<<SS, 256>>>(item2idx, cat2idx, p_et, p_ft, p_alpha, p_sgh);

    // 7. out = sg @ all_item^T  [S, V], K=256 — grid (m, n) for B L2 reuse
    { dim3 g(SS / 128, (VV + 127) / 128);
      k_hgemm<0,1><<<g, 256, SMF>>>(out, nullptr, nullptr, p_sgh, nullptr, D2, p_allh, D2, SS, VV, D2, nullptr); }
}